// round 5
// baseline (speedup 1.0000x reference)
#include <cuda_runtime.h>
#include <math.h>

#define B_ 512
#define T_ 512

// Scratch (static __device__ arrays: allocation-free per harness rules)
__device__ float g_xw0[(size_t)T_ * B_ * 16];   // layer0 input projection
__device__ float g_hlast[B_ * 70];
__device__ float g_dummy[32];

// ---------------------------------------------------------------------------
// helpers
// ---------------------------------------------------------------------------
// In-place packed FMA: acc = a*b + acc. "+l" ties addend to output (no MOVs).
__device__ __forceinline__ void ffma2_acc(float2& acc, float2 a, float2 b) {
    asm("fma.rn.f32x2 %0, %1, %2, %0;"
        : "+l"(reinterpret_cast<unsigned long long&>(acc))
        : "l"(reinterpret_cast<const unsigned long long&>(a)),
          "l"(reinterpret_cast<const unsigned long long&>(b)));
}

// tanh(x) = sign(x)*(1 - e^{-2|x|})/(1 + e^{-2|x|}); denom in [1,2]. ~1e-7 abs err.
__device__ __forceinline__ float ftanh(float x) {
    float ax = fabsf(x);
    float t = __expf(-2.f * ax);
    float r = __fdividef(1.f - t, 1.f + t);
    return copysignf(r, x);
}

__device__ __forceinline__ void cp_async16(void* smem_dst, const void* gsrc) {
    unsigned saddr = (unsigned)__cvta_generic_to_shared(smem_dst);
    asm volatile("cp.async.ca.shared.global [%0], [%1], 16;" :: "r"(saddr), "l"(gsrc));
}
#define CP_COMMIT() asm volatile("cp.async.commit_group;" ::: "memory")
#define CP_WAIT2()  asm volatile("cp.async.wait_group 2;" ::: "memory")

// dummy kernel: shifts profiler capture slot onto the fused kernel
__global__ void dummy_kernel(float* p) { if (threadIdx.x == 0) p[0] = 1.f; }

// ---------------------------------------------------------------------------
// GEMM for layer-0 input projection: xw0[t*B+b, n] = sum_k x[b,t,k]*W0[k,n]+b0[n]
// ---------------------------------------------------------------------------
template <int K, int N, int TM>
__global__ void __launch_bounds__((N / 4) * (TM / 4))
gemm0_kernel(const float* __restrict__ in, const float* __restrict__ W,
             const float* __restrict__ bias, float* __restrict__ out) {
    constexpr int NG4 = N / 4;
    constexpr int TMP = TM + 4;

    __shared__ __align__(16) float AshT[K * TMP];
    __shared__ __align__(16) float Wsh[K * N];

    const int tid  = threadIdx.x;
    const int nthr = blockDim.x;
    const int rM   = blockIdx.x * TM;

#pragma unroll 4
    for (int idx = tid; idx < K * N; idx += nthr) Wsh[idx] = W[idx];
#pragma unroll 8
    for (int idx = tid; idx < TM * K; idx += nthr) {
        int rr = idx / K, kk = idx % K;
        int r = rM + rr;
        int t = r >> 9;
        int b = r & (B_ - 1);
        AshT[kk * TMP + rr] = in[((size_t)b * T_ + t) * K + kk];
    }
    __syncthreads();

    const int tx  = tid % NG4;
    const int rid = tid / NG4;
    const int colb = 4 * tx;

    float4 bv = *(const float4*)&bias[colb];
    float4 acc0 = bv, acc1 = bv, acc2 = bv, acc3 = bv;

    const float4* Wp = (const float4*)Wsh;
#pragma unroll 4
    for (int k = 0; k < K; k++) {
        float4 a = *(const float4*)&AshT[k * TMP + rid * 4];
        float4 w = Wp[k * NG4 + tx];
        acc0.x = fmaf(a.x, w.x, acc0.x); acc0.y = fmaf(a.x, w.y, acc0.y);
        acc0.z = fmaf(a.x, w.z, acc0.z); acc0.w = fmaf(a.x, w.w, acc0.w);
        acc1.x = fmaf(a.y, w.x, acc1.x); acc1.y = fmaf(a.y, w.y, acc1.y);
        acc1.z = fmaf(a.y, w.z, acc1.z); acc1.w = fmaf(a.y, w.w, acc1.w);
        acc2.x = fmaf(a.z, w.x, acc2.x); acc2.y = fmaf(a.z, w.y, acc2.y);
        acc2.z = fmaf(a.z, w.z, acc2.z); acc2.w = fmaf(a.z, w.w, acc2.w);
        acc3.x = fmaf(a.w, w.x, acc3.x); acc3.y = fmaf(a.w, w.y, acc3.y);
        acc3.z = fmaf(a.w, w.z, acc3.z); acc3.w = fmaf(a.w, w.w, acc3.w);
    }
    float4 accs[4] = {acc0, acc1, acc2, acc3};
#pragma unroll
    for (int r = 0; r < 4; r++)
        *(float4*)&out[(size_t)(rM + rid * 4 + r) * N + colb] = accs[r];
}

// ---------------------------------------------------------------------------
// Fused wavefront RNN: all 4 layers pipelined over time in one block.
// Block = 4 batches. Layer l at tick tau computes t = tau - l.
// Hidden vectors live in shared as duplicated {h,h} float2 pairs in per-layer
// concatenated [own-h(H) ; prev-h(IN)] buffers. Weights (unit-pair packed
// columns of [U;W]) live in a SINGLE overlaid register array uw[34].
// ---------------------------------------------------------------------------
#define NBATCH   4
#define NTHREADS 352

// vin float2 offsets per layer (concat buffers)
#define VOFF0 0     /* D=16  */
#define VOFF1 16    /* D=48  */
#define VOFF2 64    /* D=96  */
#define VOFF3 160   /* D=136 (134 + 2 pad) */
#define VTOT  296

template <int HL, int C, int P, int VOFF, int VNEXT, int HNEXT, bool L0F, bool LAST>
__device__ __forceinline__ void layer_tick(
    float2 (&vin)[2][NBATCH][VTOT],
    const float (&xw0sh)[4][NBATCH][16],
    const float2 (&u2)[34],
    int jp, int p, float2 bias2,
    int prev, int cur, int tau, int t,
    float* __restrict__ hlast, int bbase)
{
    float2 acc[NBATCH], accB[NBATCH];
#pragma unroll
    for (int b = 0; b < NBATCH; b++) {
        if (L0F) acc[b] = *(const float2*)&xw0sh[tau & 3][b][2 * jp];
        else     acc[b] = make_float2(0.f, 0.f);
        accB[b] = make_float2(0.f, 0.f);
    }

#pragma unroll
    for (int r = 0; r < C / 2; r++) {
#pragma unroll
        for (int b = 0; b < NBATCH; b++) {
            float4 hh = *(const float4*)&vin[prev][b][VOFF + p * C + 2 * r];
            ffma2_acc(acc[b],  make_float2(hh.x, hh.y), u2[2 * r]);
            ffma2_acc(accB[b], make_float2(hh.z, hh.w), u2[2 * r + 1]);
        }
    }

#pragma unroll
    for (int b = 0; b < NBATCH; b++) {
        float zx = acc[b].x + accB[b].x;
        float zy = acc[b].y + accB[b].y;
#pragma unroll
        for (int m = 1; m < P; m <<= 1) {
            zx += __shfl_xor_sync(0xffffffffu, zx, m);
            zy += __shfl_xor_sync(0xffffffffu, zy, m);
        }
        if (p == 0 && 2 * jp < HL) {
            float h0 = ftanh(zx + bias2.x);
            float h1 = ftanh(zy + bias2.y);
            float4 pk = make_float4(h0, h0, h1, h1);
            *(float4*)&vin[cur][b][VOFF + 2 * jp] = pk;
            if (!LAST) {
                *(float4*)&vin[cur][b][VNEXT + HNEXT + 2 * jp] = pk;
            } else if (t == T_ - 1) {
                float2 hv = make_float2(h0, h1);
                *(float2*)&hlast[(size_t)(bbase + b) * 70 + 2 * jp] = hv;
            }
        }
    }
}

// weight gather: rows i = p*C + r of concat [U(HxH); W(INxH)], columns (2jp, 2jp+1)
template <int HL, int INL, int C>
__device__ __forceinline__ void load_w(const float* __restrict__ U,
                                       const float* __restrict__ W,
                                       int jp, int p, float2 (&u2)[34]) {
    int j0 = 2 * jp, j1 = 2 * jp + 1;
#pragma unroll
    for (int r = 0; r < C; r++) {
        int i = p * C + r;
        float a0 = 0.f, a1 = 0.f;
        if (j0 < HL) {
            if (i < HL)            { a0 = U[i * HL + j0]; a1 = U[i * HL + j1]; }
            else if (i < HL + INL) { int k = i - HL; a0 = W[k * HL + j0]; a1 = W[k * HL + j1]; }
        }
        u2[r] = make_float2(a0, a1);
    }
}

__global__ void __launch_bounds__(NTHREADS, 1)
fused_rnn_kernel(const float* __restrict__ xw0,
                 const float* __restrict__ U0,
                 const float* __restrict__ W1, const float* __restrict__ U1, const float* __restrict__ b1v,
                 const float* __restrict__ W2, const float* __restrict__ U2, const float* __restrict__ b2v,
                 const float* __restrict__ W3, const float* __restrict__ U3, const float* __restrict__ b3v,
                 float* __restrict__ hlast)
{
    __shared__ __align__(16) float2 vin[2][NBATCH][VTOT];
    __shared__ __align__(16) float xw0sh[4][NBATCH][16];

    const int tid = threadIdx.x;
    const int bbase = blockIdx.x * NBATCH;

    // warp->layer map (SMSP-balanced):
    // w0-3: L3, w4-6: L2, w7: L3, w8: L2, w9: L1, w10: L0
    int layer, slot;
    if (tid < 128)       { layer = 3; slot = tid; }
    else if (tid < 224)  { layer = 2; slot = tid - 128; }
    else if (tid < 256)  { layer = 3; slot = 128 + (tid - 224); }
    else if (tid < 288)  { layer = 2; slot = 96 + (tid - 256); }
    else if (tid < 320)  { layer = 1; slot = tid - 288; }
    else                 { layer = 0; slot = tid - 320; }

    // per-layer decode + weight load into the SINGLE overlaid register array
    int jp = 0, p = 0;
    float2 bias2 = make_float2(0.f, 0.f);
    float2 uw[34];
    if (layer == 3) {
        jp = slot >> 2; p = slot & 3;
        load_w<70, 64, 34>(U3, W3, jp, p, uw);
        if (2 * jp < 70) bias2 = make_float2(b3v[2 * jp], b3v[2 * jp + 1]);
    } else if (layer == 2) {
        jp = slot >> 2; p = slot & 3;
        load_w<64, 32, 24>(U2, W2, jp, p, uw);
        bias2 = make_float2(b2v[2 * jp], b2v[2 * jp + 1]);
    } else if (layer == 1) {
        jp = slot >> 1; p = slot & 1;
        load_w<32, 16, 24>(U1, W1, jp, p, uw);
        bias2 = make_float2(b1v[2 * jp], b1v[2 * jp + 1]);
    } else if (slot < 8) {
        jp = slot; p = 0;
        load_w<16, 0, 16>(U0, U0, jp, 0, uw);  // W unused (IN=0)
    }

    // zero both vin buffers
    for (int i = tid; i < 2 * NBATCH * VTOT; i += NTHREADS)
        (&vin[0][0][0])[i] = make_float2(0.f, 0.f);

    // preload xw0 for t = 0,1,2 (3 cp.async groups, 16B each)
    for (int d = 0; d < 3; d++) {
        if (tid < 16) {
            int b = tid >> 2, q = tid & 3;
            cp_async16(&xw0sh[d][b][4 * q],
                       &xw0[((size_t)d * B_ + bbase + b) * 16 + 4 * q]);
        }
        CP_COMMIT();
    }
    CP_WAIT2();      // t=0 ready
    __syncthreads();

    for (int tau = 0; tau < T_ + 3; tau++) {
        const int prev = (tau + 1) & 1;
        const int cur  = tau & 1;

        // stage xw0 for t = tau+3
        int t3 = tau + 3;
        if (tid < 16 && t3 < T_) {
            int b = tid >> 2, q = tid & 3;
            cp_async16(&xw0sh[t3 & 3][b][4 * q],
                       &xw0[((size_t)t3 * B_ + bbase + b) * 16 + 4 * q]);
        }
        CP_COMMIT();

        if (layer == 3) {
            int t = tau - 3;
            if (t >= 0 && t < T_)
                layer_tick<70, 34, 4, VOFF3, 0, 0, false, true>(
                    vin, xw0sh, uw, jp, p, bias2, prev, cur, tau, t, hlast, bbase);
        } else if (layer == 2) {
            int t = tau - 2;
            if (t >= 0 && t < T_)
                layer_tick<64, 24, 4, VOFF2, VOFF3, 70, false, false>(
                    vin, xw0sh, uw, jp, p, bias2, prev, cur, tau, t, hlast, bbase);
        } else if (layer == 1) {
            int t = tau - 1;
            if (t >= 0 && t < T_)
                layer_tick<32, 24, 2, VOFF1, VOFF2, 64, false, false>(
                    vin, xw0sh, uw, jp, p, bias2, prev, cur, tau, t, hlast, bbase);
        } else if (slot < 8) {
            if (tau < T_)
                layer_tick<16, 16, 1, VOFF0, VOFF1, 32, true, false>(
                    vin, xw0sh, uw, jp, 0, bias2, prev, cur, tau, tau, hlast, bbase);
        }

        CP_WAIT2();      // t = tau+1 staged copy complete before next tick
        __syncthreads();
    }
}

// ---------------------------------------------------------------------------
// Dense (70 -> 5) + softmax. One thread per batch row.
// ---------------------------------------------------------------------------
__global__ void dense_softmax_kernel(const float* __restrict__ h,
                                     const float* __restrict__ Wd,
                                     const float* __restrict__ bd,
                                     float* __restrict__ out) {
    int b = blockIdx.x * blockDim.x + threadIdx.x;
    if (b >= B_) return;
    float l[5];
#pragma unroll
    for (int c = 0; c < 5; c++) l[c] = bd[c];
    for (int k = 0; k < 70; k++) {
        float hv = h[b * 70 + k];
#pragma unroll
        for (int c = 0; c < 5; c++) l[c] = fmaf(hv, Wd[k * 5 + c], l[c]);
    }
    float m = l[0];
#pragma unroll
    for (int c = 1; c < 5; c++) m = fmaxf(m, l[c]);
    float s = 0.f;
#pragma unroll
    for (int c = 0; c < 5; c++) { l[c] = expf(l[c] - m); s += l[c]; }
    float inv = 1.f / s;
#pragma unroll
    for (int c = 0; c < 5; c++) out[b * 5 + c] = l[c] * inv;
}

// ---------------------------------------------------------------------------
extern "C" void kernel_launch(void* const* d_in, const int* in_sizes, int n_in,
                              void* d_out, int out_size) {
    const float* x  = (const float*)d_in[0];
    const float* W0 = (const float*)d_in[1];
    const float* U0 = (const float*)d_in[2];
    const float* b0 = (const float*)d_in[3];
    const float* W1 = (const float*)d_in[4];
    const float* U1 = (const float*)d_in[5];
    const float* b1 = (const float*)d_in[6];
    const float* W2 = (const float*)d_in[7];
    const float* U2 = (const float*)d_in[8];
    const float* b2 = (const float*)d_in[9];
    const float* W3 = (const float*)d_in[10];
    const float* U3 = (const float*)d_in[11];
    const float* b3 = (const float*)d_in[12];
    const float* Wd = (const float*)d_in[13];
    const float* bd = (const float*)d_in[14];
    float* out = (float*)d_out;

    static float* xw0 = nullptr;
    static float* hlast = nullptr;
    static float* dummy = nullptr;
    if (!xw0) {
        cudaGetSymbolAddress((void**)&xw0, g_xw0);
        cudaGetSymbolAddress((void**)&hlast, g_hlast);
        cudaGetSymbolAddress((void**)&dummy, g_dummy);
    }

    const int M = T_ * B_;  // 262144

    // dummy launch: shifts ncu's capture slot onto the fused kernel
    dummy_kernel<<<1, 32>>>(dummy);

    // Layer-0 input projection: x [B,T,78] -> xw0 [T,B,16] (bias folded)
    gemm0_kernel<78, 16, 128><<<M / 128, 4 * 32>>>(x, W0, b0, xw0);

    // Fused wavefront RNN over all 4 layers
    fused_rnn_kernel<<<B_ / NBATCH, NTHREADS>>>(xw0, U0,
                                                W1, U1, b1,
                                                W2, U2, b2,
                                                W3, U3, b3,
                                                hlast);

    // Dense + softmax
    dense_softmax_kernel<<<2, 256>>>(hlast, Wd, bd, out);
}

// round 6
// speedup vs baseline: 1.4776x; 1.4776x over previous
#include <cuda_runtime.h>
#include <math.h>

#define B_ 512
#define T_ 512

// Scratch (static __device__ arrays: allocation-free per harness rules)
__device__ float g_xw0[(size_t)T_ * B_ * 16];   // layer0 input projection
__device__ float g_hlast[B_ * 70];

// ---------------------------------------------------------------------------
// helpers
// ---------------------------------------------------------------------------
__device__ __forceinline__ void ffma2_acc(float2& acc, float2 a, float2 b) {
    asm("fma.rn.f32x2 %0, %1, %2, %0;"
        : "+l"(reinterpret_cast<unsigned long long&>(acc))
        : "l"(reinterpret_cast<const unsigned long long&>(a)),
          "l"(reinterpret_cast<const unsigned long long&>(b)));
}

// tanh(x) = sign(x)*(1 - e^{-2|x|})/(1 + e^{-2|x|}); denom in [1,2]. ~1e-7 abs err.
__device__ __forceinline__ float ftanh(float x) {
    float ax = fabsf(x);
    float t = __expf(-2.f * ax);
    float r = __fdividef(1.f - t, 1.f + t);
    return copysignf(r, x);
}

__device__ __forceinline__ void cp_async16(void* smem_dst, const void* gsrc) {
    unsigned saddr = (unsigned)__cvta_generic_to_shared(smem_dst);
    asm volatile("cp.async.ca.shared.global [%0], [%1], 16;" :: "r"(saddr), "l"(gsrc));
}
#define CP_COMMIT() asm volatile("cp.async.commit_group;" ::: "memory")
#define CP_WAIT2()  asm volatile("cp.async.wait_group 2;" ::: "memory")

// ---------------------------------------------------------------------------
// GEMM for layer-0 input projection: xw0[t*B+b, n] = sum_k x[b,t,k]*W0[k,n]+b0[n]
// Incremental index stepping (no div/mod in the hot loops).
// ---------------------------------------------------------------------------
template <int K, int N, int TM>
__global__ void __launch_bounds__((N / 4) * (TM / 4))
gemm0_kernel(const float* __restrict__ in, const float* __restrict__ W,
             const float* __restrict__ bias, float* __restrict__ out) {
    constexpr int NG4 = N / 4;
    constexpr int TMP = TM + 4;
    constexpr int NTHR = NG4 * (TM / 4);

    __shared__ __align__(16) float AshT[K * TMP];
    __shared__ __align__(16) float Wsh[K * N];

    const int tid = threadIdx.x;
    const int rM  = blockIdx.x * TM;

    for (int idx = tid; idx < K * N; idx += NTHR) Wsh[idx] = W[idx];

    // A tile: r = rM + rr; t = rM>>9 is block-constant (TM=128 divides 512)
    {
        const int tblk = rM >> 9;
        const int b0r  = rM & (B_ - 1);
        int idx = tid;
        int rr = idx / K;
        int kk = idx - rr * K;
        int g  = (b0r + rr) * (T_ * K) + tblk * K + kk;
        int sa = kk * TMP + rr;
        const int GR = T_ * K;     // advance per rr
#pragma unroll 4
        for (int it = 0; it < (TM * K) / NTHR; it++) {
            AshT[sa] = in[g];
            kk += NTHR; g += NTHR; sa += NTHR * TMP;
            if (kk >= K) { kk -= K; g += GR - K; sa += 1 - K * TMP; }
            if (kk >= K) { kk -= K; g += GR - K; sa += 1 - K * TMP; }
        }
    }
    __syncthreads();

    const int tx  = tid % NG4;
    const int rid = tid / NG4;
    const int colb = 4 * tx;

    float4 bv = *(const float4*)&bias[colb];
    float4 acc0 = bv, acc1 = bv, acc2 = bv, acc3 = bv;

    const float4* Wp = (const float4*)Wsh;
#pragma unroll 4
    for (int k = 0; k < K; k++) {
        float4 a = *(const float4*)&AshT[k * TMP + rid * 4];
        float4 w = Wp[k * NG4 + tx];
        acc0.x = fmaf(a.x, w.x, acc0.x); acc0.y = fmaf(a.x, w.y, acc0.y);
        acc0.z = fmaf(a.x, w.z, acc0.z); acc0.w = fmaf(a.x, w.w, acc0.w);
        acc1.x = fmaf(a.y, w.x, acc1.x); acc1.y = fmaf(a.y, w.y, acc1.y);
        acc1.z = fmaf(a.y, w.z, acc1.z); acc1.w = fmaf(a.y, w.w, acc1.w);
        acc2.x = fmaf(a.z, w.x, acc2.x); acc2.y = fmaf(a.z, w.y, acc2.y);
        acc2.z = fmaf(a.z, w.z, acc2.z); acc2.w = fmaf(a.z, w.w, acc2.w);
        acc3.x = fmaf(a.w, w.x, acc3.x); acc3.y = fmaf(a.w, w.y, acc3.y);
        acc3.z = fmaf(a.w, w.z, acc3.z); acc3.w = fmaf(a.w, w.w, acc3.w);
    }
    float4 accs[4] = {acc0, acc1, acc2, acc3};
#pragma unroll
    for (int r = 0; r < 4; r++)
        *(float4*)&out[(size_t)(rM + rid * 4 + r) * N + colb] = accs[r];
}

// ---------------------------------------------------------------------------
// Fused wavefront RNN, v3. 9 warps / block, block = 4 batches.
// Partition: L3 (H=70): warps 0-4, P=4, C=34. L2 (H=64): warps 5-6, P=2, C=48.
// L1 (H=32): warp 7, P=1, C=48. L0 (H=16): warp 8, P=1, C=16.
// Reduction: FULL butterfly over P lanes -> every lane holds all 4 batch sums;
// each lane then owns 4/P batches for tanh+store (cuts MUFU/STS by P).
// ---------------------------------------------------------------------------
#define NBATCH   4
#define NTHREADS 288

#define VOFF0 0     /* D=16  */
#define VOFF1 16    /* D=48  */
#define VOFF2 64    /* D=96  */
#define VOFF3 160   /* D=136 (134 + 2 pad) */
#define VTOT  296

template <int HL, int C, int P, int VOFF, int VNEXT, int HNEXT, bool L0F, bool LAST>
__device__ __forceinline__ void layer_tick(
    float2 (&vin)[2][NBATCH][VTOT],
    const float (&xw0sh)[4][NBATCH][16],
    const float2 (&u2)[48],
    int jp, int p, float2 bias2, bool jv,
    int prev, int cur, int tau, int t,
    float* __restrict__ hlast, int bbase)
{
    float2 acc[NBATCH], accB[NBATCH];
#pragma unroll
    for (int b = 0; b < NBATCH; b++) {
        if (L0F) acc[b] = *(const float2*)&xw0sh[tau & 3][b][2 * jp];
        else     acc[b] = make_float2(0.f, 0.f);
        accB[b] = make_float2(0.f, 0.f);
    }

#pragma unroll
    for (int r = 0; r < C / 2; r++) {
#pragma unroll
        for (int b = 0; b < NBATCH; b++) {
            float4 hh = *(const float4*)&vin[prev][b][VOFF + p * C + 2 * r];
            ffma2_acc(acc[b],  make_float2(hh.x, hh.y), u2[2 * r]);
            ffma2_acc(accB[b], make_float2(hh.z, hh.w), u2[2 * r + 1]);
        }
    }

    float zx[NBATCH], zy[NBATCH];
#pragma unroll
    for (int b = 0; b < NBATCH; b++) {
        zx[b] = acc[b].x + accB[b].x;
        zy[b] = acc[b].y + accB[b].y;
    }
    // full butterfly allreduce over the P partner lanes
#pragma unroll
    for (int m = 1; m < P; m <<= 1) {
#pragma unroll
        for (int b = 0; b < NBATCH; b++) {
            zx[b] += __shfl_xor_sync(0xffffffffu, zx[b], m);
            zy[b] += __shfl_xor_sync(0xffffffffu, zy[b], m);
        }
    }

    // lane p owns batches [p*(4/P), ...)
    auto emit = [&](int b, float sx, float sy) {
        if (jv) {
            float h0 = ftanh(sx + bias2.x);
            float h1 = ftanh(sy + bias2.y);
            float4 pk = make_float4(h0, h0, h1, h1);
            *(float4*)&vin[cur][b][VOFF + 2 * jp] = pk;
            if (!LAST) {
                *(float4*)&vin[cur][b][VNEXT + HNEXT + 2 * jp] = pk;
            } else if (t == T_ - 1) {
                float2 hv = make_float2(h0, h1);
                *(float2*)&hlast[(size_t)(bbase + b) * 70 + 2 * jp] = hv;
            }
        }
    };

    if constexpr (P == 4) {
        float rx = (p & 1) ? ((p & 2) ? zx[3] : zx[1]) : ((p & 2) ? zx[2] : zx[0]);
        float ry = (p & 1) ? ((p & 2) ? zy[3] : zy[1]) : ((p & 2) ? zy[2] : zy[0]);
        emit(p, rx, ry);
    } else if constexpr (P == 2) {
        float rx0 = p ? zx[2] : zx[0];
        float ry0 = p ? zy[2] : zy[0];
        float rx1 = p ? zx[3] : zx[1];
        float ry1 = p ? zy[3] : zy[1];
        emit(2 * p, rx0, ry0);
        emit(2 * p + 1, rx1, ry1);
    } else {
#pragma unroll
        for (int q = 0; q < NBATCH; q++) emit(q, zx[q], zy[q]);
    }
}

// weight gather: rows i = p*C + r of concat [U(HxH); W(INxH)], columns (2jp, 2jp+1)
template <int HL, int INL, int C>
__device__ __forceinline__ void load_w(const float* __restrict__ U,
                                       const float* __restrict__ W,
                                       int jp, int p, float2 (&u2)[48]) {
    int j0 = 2 * jp, j1 = 2 * jp + 1;
#pragma unroll
    for (int r = 0; r < C; r++) {
        int i = p * C + r;
        float a0 = 0.f, a1 = 0.f;
        if (j0 < HL) {
            if (i < HL)            { a0 = U[i * HL + j0]; a1 = U[i * HL + j1]; }
            else if (i < HL + INL) { int k = i - HL; a0 = W[k * HL + j0]; a1 = W[k * HL + j1]; }
        }
        u2[r] = make_float2(a0, a1);
    }
}

__global__ void __launch_bounds__(NTHREADS, 1)
fused_rnn_kernel(const float* __restrict__ xw0,
                 const float* __restrict__ U0,
                 const float* __restrict__ W1, const float* __restrict__ U1, const float* __restrict__ b1v,
                 const float* __restrict__ W2, const float* __restrict__ U2, const float* __restrict__ b2v,
                 const float* __restrict__ W3, const float* __restrict__ U3, const float* __restrict__ b3v,
                 float* __restrict__ hlast)
{
    __shared__ __align__(16) float2 vin[2][NBATCH][VTOT];
    __shared__ __align__(16) float xw0sh[4][NBATCH][16];

    const int tid = threadIdx.x;
    const int wid = tid >> 5;
    const int bbase = blockIdx.x * NBATCH;

    // warp->layer map: w0-4: L3, w5-6: L2, w7: L1, w8: L0
    // SMSP (wid%4): 0:{L3,L3,L0} 1:{L3,L2} 2:{L3,L2} 3:{L3,L1}
    int layer, slot;
    if (wid < 5)      { layer = 3; slot = tid; }
    else if (wid < 7) { layer = 2; slot = tid - 160; }
    else if (wid < 8) { layer = 1; slot = tid - 224; }
    else              { layer = 0; slot = tid - 256; }

    int jp = 0, p = 0;
    bool jv = false;
    float2 bias2 = make_float2(0.f, 0.f);
    float2 uw[48];
    if (layer == 3) {
        jp = slot >> 2; p = slot & 3;
        jv = (jp < 35);
        load_w<70, 64, 34>(U3, W3, jp, p, uw);
        if (jv) bias2 = make_float2(b3v[2 * jp], b3v[2 * jp + 1]);
    } else if (layer == 2) {
        jp = slot >> 1; p = slot & 1;
        jv = true;
        load_w<64, 32, 48>(U2, W2, jp, p, uw);
        bias2 = make_float2(b2v[2 * jp], b2v[2 * jp + 1]);
    } else if (layer == 1) {
        jp = slot; p = 0;
        jv = (jp < 16);
        load_w<32, 16, 48>(U1, W1, jp, 0, uw);
        if (jv) bias2 = make_float2(b1v[2 * jp], b1v[2 * jp + 1]);
    } else {
        jp = slot; p = 0;
        jv = (jp < 8);
        load_w<16, 0, 16>(U0, U0, jp, 0, uw);   // W unused (IN=0)
    }

    // zero both vin buffers
    for (int i = tid; i < 2 * NBATCH * VTOT; i += NTHREADS)
        (&vin[0][0][0])[i] = make_float2(0.f, 0.f);

    // preload xw0 for t = 0,1,2 (3 cp.async groups, 16B each)
    for (int d = 0; d < 3; d++) {
        if (tid < 16) {
            int b = tid >> 2, q = tid & 3;
            cp_async16(&xw0sh[d][b][4 * q],
                       &xw0[((size_t)d * B_ + bbase + b) * 16 + 4 * q]);
        }
        CP_COMMIT();
    }
    CP_WAIT2();      // t=0 ready
    __syncthreads();

    for (int tau = 0; tau < T_ + 3; tau++) {
        const int prev = (tau + 1) & 1;
        const int cur  = tau & 1;

        // stage xw0 for t = tau+3
        int t3 = tau + 3;
        if (tid < 16 && t3 < T_) {
            int b = tid >> 2, q = tid & 3;
            cp_async16(&xw0sh[t3 & 3][b][4 * q],
                       &xw0[((size_t)t3 * B_ + bbase + b) * 16 + 4 * q]);
        }
        CP_COMMIT();

        if (layer == 3) {
            int t = tau - 3;
            if (t >= 0 && t < T_)
                layer_tick<70, 34, 4, VOFF3, 0, 0, false, true>(
                    vin, xw0sh, uw, jp, p, bias2, jv, prev, cur, tau, t, hlast, bbase);
        } else if (layer == 2) {
            int t = tau - 2;
            if (t >= 0 && t < T_)
                layer_tick<64, 48, 2, VOFF2, VOFF3, 70, false, false>(
                    vin, xw0sh, uw, jp, p, bias2, jv, prev, cur, tau, t, hlast, bbase);
        } else if (layer == 1) {
            int t = tau - 1;
            if (t >= 0 && t < T_)
                layer_tick<32, 48, 1, VOFF1, VOFF2, 64, false, false>(
                    vin, xw0sh, uw, jp, 0, bias2, jv, prev, cur, tau, t, hlast, bbase);
        } else {
            if (tau < T_)
                layer_tick<16, 16, 1, VOFF0, VOFF1, 32, true, false>(
                    vin, xw0sh, uw, jp, 0, bias2, jv, prev, cur, tau, tau, hlast, bbase);
        }

        CP_WAIT2();
        __syncthreads();
    }
}

// ---------------------------------------------------------------------------
// Dense (70 -> 5) + softmax, smem-staged. grid 4 x block 128.
// ---------------------------------------------------------------------------
__global__ void __launch_bounds__(128)
dense_softmax_kernel(const float* __restrict__ h,
                     const float* __restrict__ Wd,
                     const float* __restrict__ bd,
                     float* __restrict__ out) {
    __shared__ float hs[128 * 70];
    __shared__ float Wds[70 * 5 + 5];

    const int tid = threadIdx.x;
    const int b0  = blockIdx.x * 128;

    for (int idx = tid; idx < 128 * 70; idx += 128)
        hs[idx] = h[(size_t)b0 * 70 + idx];
    for (int idx = tid; idx < 355; idx += 128)
        Wds[idx] = (idx < 350) ? Wd[idx] : bd[idx - 350];
    __syncthreads();

    float l[5];
#pragma unroll
    for (int c = 0; c < 5; c++) l[c] = Wds[350 + c];
#pragma unroll 2
    for (int k = 0; k < 70; k++) {
        float hv = hs[tid * 70 + k];
#pragma unroll
        for (int c = 0; c < 5; c++) l[c] = fmaf(hv, Wds[k * 5 + c], l[c]);
    }
    float m = l[0];
#pragma unroll
    for (int c = 1; c < 5; c++) m = fmaxf(m, l[c]);
    float s = 0.f;
#pragma unroll
    for (int c = 0; c < 5; c++) { l[c] = expf(l[c] - m); s += l[c]; }
    float inv = 1.f / s;
#pragma unroll
    for (int c = 0; c < 5; c++) out[(size_t)(b0 + tid) * 5 + c] = l[c] * inv;
}

// ---------------------------------------------------------------------------
extern "C" void kernel_launch(void* const* d_in, const int* in_sizes, int n_in,
                              void* d_out, int out_size) {
    const float* x  = (const float*)d_in[0];
    const float* W0 = (const float*)d_in[1];
    const float* U0 = (const float*)d_in[2];
    const float* b0 = (const float*)d_in[3];
    const float* W1 = (const float*)d_in[4];
    const float* U1 = (const float*)d_in[5];
    const float* b1 = (const float*)d_in[6];
    const float* W2 = (const float*)d_in[7];
    const float* U2 = (const float*)d_in[8];
    const float* b2 = (const float*)d_in[9];
    const float* W3 = (const float*)d_in[10];
    const float* U3 = (const float*)d_in[11];
    const float* b3 = (const float*)d_in[12];
    const float* Wd = (const float*)d_in[13];
    const float* bd = (const float*)d_in[14];
    float* out = (float*)d_out;

    static float* xw0 = nullptr;
    static float* hlast = nullptr;
    if (!xw0) {
        cudaGetSymbolAddress((void**)&xw0, g_xw0);
        cudaGetSymbolAddress((void**)&hlast, g_hlast);
    }

    const int M = T_ * B_;  // 262144

    gemm0_kernel<78, 16, 128><<<M / 128, 4 * 32>>>(x, W0, b0, xw0);

    fused_rnn_kernel<<<B_ / NBATCH, NTHREADS>>>(xw0, U0,
                                                W1, U1, b1,
                                                W2, U2, b2,
                                                W3, U3, b3,
                                                hlast);

    dense_softmax_kernel<<<4, 128>>>(hlast, Wd, bd, out);
}